// round 16
// baseline (speedup 1.0000x reference)
#include <cuda_runtime.h>
#include <cstdint>

#define NNODES 100000
#define NFEAT  128
#define HID    128   // 8 heads * 16
#define H1     8
#define NCLS   40
#define NEG    0.2f
#define EMAX   1664000
#define SCAN_BLKS 98   // ceil(100000/1024)

typedef unsigned long long ull;

// ---------------- scratch (device globals; no runtime alloc) ----------------
__device__ __align__(16) float g_h1  [NNODES * HID];
__device__ __align__(16) float g_res1[NNODES * HID];
__device__ __align__(16) float g_as1 [NNODES * H1];
__device__ __align__(16) float g_ad1 [NNODES * H1];
__device__ __align__(16) float g_h2  [NNODES * NCLS];
__device__ __align__(16) float g_res2[NNODES * NCLS];
__device__ __align__(16) float g_as2 [NNODES];
__device__ __align__(16) float g_ad2 [NNODES];
__device__ int g_deg[NNODES];
__device__ int g_off[NNODES + 1];
__device__ int g_cur[NNODES];
__device__ int g_csr[EMAX];
__device__ int g_bsum[128];
__device__ int g_is64;

// ---------------- f32x2 helpers ----------------------------------------------
__device__ __forceinline__ ull pack2(float v) {
    ull r; asm("mov.b64 %0, {%1,%1};" : "=l"(r) : "f"(v)); return r;
}
__device__ __forceinline__ void unpack2(ull v, float& lo, float& hi) {
    asm("mov.b64 {%0,%1}, %2;" : "=f"(lo), "=f"(hi) : "l"(v));
}
__device__ __forceinline__ void fma2(ull& acc, ull a, ull b) {
    asm("fma.rn.f32x2 %0, %1, %2, %0;" : "+l"(acc) : "l"(a), "l"(b));
}
__device__ __forceinline__ ull mul2(ull a, ull b) {
    ull c; asm("mul.rn.f32x2 %0, %1, %2;" : "=l"(c) : "l"(a), "l"(b)); return c;
}
__device__ __forceinline__ ull add2(ull a, ull b) {
    ull c; asm("add.rn.f32x2 %0, %1, %2;" : "=l"(c) : "l"(a), "l"(b)); return c;
}
__device__ __forceinline__ ull shfl_xor64(ull v, int o) {
    double d = __longlong_as_double((long long)v);
    d = __shfl_xor_sync(0xffffffffu, d, o);
    return (ull)__double_as_longlong(d);
}

// ---------------- edge_index dtype detection (warp-parallel) ------------------
__global__ void k_detect(const int* __restrict__ ei32)
{
    const int lane = threadIdx.x & 31;
    long long s = (long long)ei32[2 * lane + 1] + (long long)ei32[2 * lane + 65];
#pragma unroll
    for (int o = 16; o; o >>= 1)
        s += __shfl_xor_sync(0xffffffffu, s, o);
    if (lane == 0) g_is64 = (s == 0) ? 1 : 0;
}

__device__ __forceinline__ int edge_dst(const int* __restrict__ ei, int E, int e)
{
    return g_is64 ? (int)((const long long*)ei)[E + e] : ei[E + e];
}
__device__ __forceinline__ int edge_src(const int* __restrict__ ei, int E, int e)
{
    return g_is64 ? (int)((const long long*)ei)[e] : ei[e];
}

// ---------------- CSR build ----------------------------------------------------
__global__ void k_zero()
{
    const int i = blockIdx.x * blockDim.x + threadIdx.x;
    if (i < NNODES) { g_deg[i] = 0; g_cur[i] = 0; }
}

__global__ void k_hist(const int* __restrict__ ei, int E)
{
    const int e = blockIdx.x * blockDim.x + threadIdx.x;
    if (e >= E) return;
    atomicAdd(&g_deg[edge_dst(ei, E, e)], 1);
}

__global__ void __launch_bounds__(1024) k_scanA()
{
    __shared__ int wsum[32];
    const int t = threadIdx.x, lane = t & 31, wid = t >> 5;
    const int idx = blockIdx.x * 1024 + t;
    const int v = (idx < NNODES) ? g_deg[idx] : 0;

    int inc = v;
#pragma unroll
    for (int o = 1; o < 32; o <<= 1) {
        int n = __shfl_up_sync(0xffffffffu, inc, o);
        if (lane >= o) inc += n;
    }
    if (lane == 31) wsum[wid] = inc;
    __syncthreads();
    if (wid == 0) {
        int s = wsum[lane];
#pragma unroll
        for (int o = 1; o < 32; o <<= 1) {
            int n = __shfl_up_sync(0xffffffffu, s, o);
            if (lane >= o) s += n;
        }
        wsum[lane] = s;
    }
    __syncthreads();
    const int pre = (wid > 0) ? wsum[wid - 1] : 0;
    if (idx < NNODES) g_off[idx] = pre + inc - v;
    if (t == 1023) g_bsum[blockIdx.x] = pre + inc;
}

__global__ void k_scanB()
{
    __shared__ int sh[128];
    const int t = threadIdx.x;
    const int v = (t < SCAN_BLKS) ? g_bsum[t] : 0;
    sh[t] = v;
    __syncthreads();
#pragma unroll
    for (int o = 1; o < 128; o <<= 1) {
        const int n = (t >= o) ? sh[t - o] : 0;
        __syncthreads();
        sh[t] += n;
        __syncthreads();
    }
    g_bsum[t] = sh[t] - v;
    if (t == 127) g_off[NNODES] = sh[127];
}

__global__ void __launch_bounds__(1024) k_scanC()
{
    const int idx = blockIdx.x * 1024 + threadIdx.x;
    if (idx < NNODES) g_off[idx] += g_bsum[blockIdx.x];
}

__global__ void k_scatter(const int* __restrict__ ei, int E)
{
    const int e = blockIdx.x * blockDim.x + threadIdx.x;
    if (e >= E) return;
    const int d = edge_dst(ei, E, e);
    const int s = edge_src(ei, E, e);
    const int pos = g_off[d] + atomicAdd(&g_cur[d], 1);
    g_csr[pos] = s;
}

// ---------------- Layer 1 node GEMM (f32x2): 32 rows x 256 cols per block ----
__global__ void __launch_bounds__(128) k_gemm1(
        const float* __restrict__ x,
        const float* __restrict__ W1,
        const float* __restrict__ resW,
        const float* __restrict__ res_b,
        const float* __restrict__ att_src,
        const float* __restrict__ att_dst)
{
    __shared__ __align__(16) float xs[128 * 36];  // [k][36]
    const int row0 = blockIdx.x * 32;
    const int t = threadIdx.x;

#pragma unroll 4
    for (int r = 0; r < 32; r++)
        xs[t * 36 + r] = x[(row0 + r) * NFEAT + t];
    __syncthreads();

    ull accA[16], accB[16];
#pragma unroll
    for (int i = 0; i < 16; i++) { accA[i] = 0ull; accB[i] = 0ull; }

    const float* WA = W1 + t;     // stride 128
    const float* WB = resW + t;   // stride 128

#pragma unroll 4
    for (int k = 0; k < 128; k++) {
        const ull wa = pack2(WA[k * 128]);
        const ull wb = pack2(WB[k * 128]);
        const ulonglong2* xp = (const ulonglong2*)(xs + k * 36);
#pragma unroll
        for (int i = 0; i < 8; i++) {
            const ulonglong2 xv = xp[i];
            fma2(accA[2 * i],     xv.x, wa);
            fma2(accA[2 * i + 1], xv.y, wa);
            fma2(accB[2 * i],     xv.x, wb);
            fma2(accB[2 * i + 1], xv.y, wb);
        }
    }

    const ull asp = pack2(att_src[t]);   // (8,16) row-major: head=t>>4
    const ull adp = pack2(att_dst[t]);
    const ull bbp = pack2(res_b[t]);
    const int head = t >> 4;

#pragma unroll
    for (int i = 0; i < 16; i++) {
        const int gr = row0 + 2 * i;
        float lo, hi;
        unpack2(accA[i], lo, hi);
        g_h1[gr * HID + t]       = lo;
        g_h1[(gr + 1) * HID + t] = hi;

        ull vs = mul2(accA[i], asp);
        ull vd = mul2(accA[i], adp);
#pragma unroll
        for (int o = 8; o; o >>= 1) {
            vs = add2(vs, shfl_xor64(vs, o));
            vd = add2(vd, shfl_xor64(vd, o));
        }
        if ((t & 15) == 0) {
            float s0, s1, d0, d1;
            unpack2(vs, s0, s1); unpack2(vd, d0, d1);
            g_as1[gr * H1 + head]       = s0;
            g_as1[(gr + 1) * H1 + head] = s1;
            g_ad1[gr * H1 + head]       = d0;
            g_ad1[(gr + 1) * H1 + head] = d1;
        }

        ull rb = add2(accB[i], bbp);
        unpack2(rb, lo, hi);
        g_res1[gr * HID + t]       = lo;
        g_res1[(gr + 1) * HID + t] = hi;
    }
}

// ---------------- FUSED: Layer-1 aggregation + Layer-2 node GEMM -------------
// 160 threads, 64-row tiles. Phase 1: 5 warps aggregate the block's 64 dst
// nodes (warp-per-node RR), finalize h = elu(num/den+b1)+res1, and write it
// straight into the transposed smem tile. Phase 2: gemm2 (unchanged).
__global__ void __launch_bounds__(160) k_agg_gemm2(
        const float* __restrict__ bias1,
        const float* __restrict__ W2,
        const float* __restrict__ res2W,
        const float* __restrict__ res2_b,
        const float* __restrict__ att_src2,
        const float* __restrict__ att_dst2)
{
    __shared__ __align__(16) float xs[128 * 68];   // [c][68]; reused as sred
    const int row0 = blockIdx.x * 64;
    const int t = threadIdx.x;
    const int wid  = t >> 5;            // 0..4
    const int lane = t & 31;

    // ---- phase 1: aggregate this block's nodes directly into xs ----
    for (int r = wid; r < 64; r += 5) {
        const int d = row0 + r;
        float4 o;
        if (d < NNODES) {
            const int h = lane >> 2;
            const float ad = g_ad1[d * H1 + h];

            float l = g_as1[d * H1 + h] + ad;      // self loop
            l = (l > 0.f) ? l : NEG * l;
            float den = __expf(l);
            float4 v = ((const float4*)(g_h1 + (size_t)d * HID))[lane];
            float4 acc; acc.x = v.x * den; acc.y = v.y * den;
            acc.z = v.z * den; acc.w = v.w * den;

            const int end = g_off[d + 1];
            int e = g_off[d];
            for (; e + 2 <= end; e += 2) {
                const int s0 = g_csr[e];
                const int s1 = g_csr[e + 1];
                float l0 = g_as1[s0 * H1 + h] + ad;
                float l1 = g_as1[s1 * H1 + h] + ad;
                l0 = (l0 > 0.f) ? l0 : NEG * l0;
                l1 = (l1 > 0.f) ? l1 : NEG * l1;
                const float w0 = __expf(l0);
                const float w1 = __expf(l1);
                den += w0 + w1;
                const float4 u0 = ((const float4*)(g_h1 + (size_t)s0 * HID))[lane];
                const float4 u1 = ((const float4*)(g_h1 + (size_t)s1 * HID))[lane];
                acc.x += u0.x * w0; acc.y += u0.y * w0;
                acc.z += u0.z * w0; acc.w += u0.w * w0;
                acc.x += u1.x * w1; acc.y += u1.y * w1;
                acc.z += u1.z * w1; acc.w += u1.w * w1;
            }
            if (e < end) {
                const int s = g_csr[e];
                float ls = g_as1[s * H1 + h] + ad;
                ls = (ls > 0.f) ? ls : NEG * ls;
                const float ew = __expf(ls);
                den += ew;
                const float4 u = ((const float4*)(g_h1 + (size_t)s * HID))[lane];
                acc.x += u.x * ew; acc.y += u.y * ew;
                acc.z += u.z * ew; acc.w += u.w * ew;
            }

            const float inv = __fdividef(1.f, den);
            const float4 b  = ((const float4*)bias1)[lane];
            const float4 rr = ((const float4*)(g_res1 + (size_t)d * HID))[lane];
            float t0;
            t0 = acc.x * inv + b.x; o.x = ((t0 > 0.f) ? t0 : (__expf(t0) - 1.f)) + rr.x;
            t0 = acc.y * inv + b.y; o.y = ((t0 > 0.f) ? t0 : (__expf(t0) - 1.f)) + rr.y;
            t0 = acc.z * inv + b.z; o.z = ((t0 > 0.f) ? t0 : (__expf(t0) - 1.f)) + rr.z;
            t0 = acc.w * inv + b.w; o.w = ((t0 > 0.f) ? t0 : (__expf(t0) - 1.f)) + rr.w;
        } else {
            o.x = o.y = o.z = o.w = 0.f;
        }
        // transposed store into the gemm tile: cols 4*lane..4*lane+3, row r
        xs[(4 * lane + 0) * 68 + r] = o.x;
        xs[(4 * lane + 1) * 68 + r] = o.y;
        xs[(4 * lane + 2) * 68 + r] = o.z;
        xs[(4 * lane + 3) * 68 + r] = o.w;
    }
    __syncthreads();

    // ---- phase 2: layer-2 GEMM (f32x2), dual-col threads ----
    const int col = t % 40;
    const int grp = t / 40;

    ull accA[8], accB[8];
#pragma unroll
    for (int i = 0; i < 8; i++) { accA[i] = 0ull; accB[i] = 0ull; }

    const float* WA = W2 + col;
    const float* WB = res2W + col;
#pragma unroll 4
    for (int k = 0; k < 128; k++) {
        const ull wa = pack2(WA[k * NCLS]);
        const ull wb = pack2(WB[k * NCLS]);
        const ulonglong2* xp = (const ulonglong2*)(xs + k * 68 + grp * 16);
#pragma unroll
        for (int i = 0; i < 4; i++) {
            const ulonglong2 xv = xp[i];
            fma2(accA[2 * i],     xv.x, wa);
            fma2(accA[2 * i + 1], xv.y, wa);
            fma2(accB[2 * i],     xv.x, wb);
            fma2(accB[2 * i + 1], xv.y, wb);
        }
    }
    __syncthreads();
    float* sred = xs;

    const float as = att_src2[col];
    const float adw = att_dst2[col];
    const ull bp = pack2(res2_b[col]);
#pragma unroll
    for (int i = 0; i < 8; i++) {
        const int lr = grp * 16 + 2 * i;
        const int gr = row0 + lr;
        float lo, hi;
        unpack2(accA[i], lo, hi);
        sred[lr * NCLS + col]       = lo * as;
        sred[(lr + 1) * NCLS + col] = hi * as;
        sred[64 * NCLS + lr * NCLS + col]       = lo * adw;
        sred[64 * NCLS + (lr + 1) * NCLS + col] = hi * adw;
        float rlo, rhi;
        unpack2(add2(accB[i], bp), rlo, rhi);
        if (gr < NNODES) {
            g_h2  [gr * NCLS + col] = lo;
            g_res2[gr * NCLS + col] = rlo;
        }
        if (gr + 1 < NNODES) {
            g_h2  [(gr + 1) * NCLS + col] = hi;
            g_res2[(gr + 1) * NCLS + col] = rhi;
        }
    }
    __syncthreads();

    if (t < 64 && row0 + t < NNODES) {
        float ss = 0.f, dd = 0.f;
#pragma unroll 8
        for (int c = 0; c < NCLS; c++) {
            ss += sred[t * NCLS + c];
            dd += sred[64 * NCLS + t * NCLS + c];
        }
        g_as2[row0 + t] = ss;
        g_ad2[row0 + t] = dd;
    }
}

// ---------------- Layer 2 aggregation + log_softmax: warp per dst node -------
__global__ void k_edge2fin(const float* __restrict__ bias2,
                           float* __restrict__ out)
{
    const int d    = (blockIdx.x * blockDim.x + threadIdx.x) >> 5;
    const int lane = threadIdx.x & 31;
    if (d >= NNODES) return;

    const int grp = lane / 10;
    const int sub = lane - grp * 10;
    const float ad = g_ad2[d];

    float den = 0.f;
    float4 acc; acc.x = acc.y = acc.z = acc.w = 0.f;

    if (grp == 0) {
        float l = g_as2[d] + ad;
        l = (l > 0.f) ? l : NEG * l;
        const float w = __expf(l);
        den = w;
        const float4 v = ((const float4*)(g_h2 + (size_t)d * NCLS))[sub];
        acc.x = v.x * w; acc.y = v.y * w; acc.z = v.z * w; acc.w = v.w * w;
    }

    if (grp < 3) {
        const int end = g_off[d + 1];
        int e = g_off[d] + grp;
        for (; e + 3 < end; e += 6) {
            const int s0 = g_csr[e];
            const int s1 = g_csr[e + 3];
            float l0 = g_as2[s0] + ad;
            float l1 = g_as2[s1] + ad;
            l0 = (l0 > 0.f) ? l0 : NEG * l0;
            l1 = (l1 > 0.f) ? l1 : NEG * l1;
            const float w0 = __expf(l0);
            const float w1 = __expf(l1);
            den += w0 + w1;
            const float4 v0 = ((const float4*)(g_h2 + (size_t)s0 * NCLS))[sub];
            const float4 v1 = ((const float4*)(g_h2 + (size_t)s1 * NCLS))[sub];
            acc.x += v0.x * w0; acc.y += v0.y * w0;
            acc.z += v0.z * w0; acc.w += v0.w * w0;
            acc.x += v1.x * w1; acc.y += v1.y * w1;
            acc.z += v1.z * w1; acc.w += v1.w * w1;
        }
        if (e < end) {
            const int s = g_csr[e];
            float l = g_as2[s] + ad;
            l = (l > 0.f) ? l : NEG * l;
            const float w = __expf(l);
            den += w;
            const float4 v = ((const float4*)(g_h2 + (size_t)s * NCLS))[sub];
            acc.x += v.x * w; acc.y += v.y * w;
            acc.z += v.z * w; acc.w += v.w * w;
        }
    }

    const unsigned FULL = 0xffffffffu;
    float den_t = den + __shfl_sync(FULL, den, lane + 10)
                      + __shfl_sync(FULL, den, lane + 20);
    float ax = acc.x + __shfl_sync(FULL, acc.x, lane + 10) + __shfl_sync(FULL, acc.x, lane + 20);
    float ay = acc.y + __shfl_sync(FULL, acc.y, lane + 10) + __shfl_sync(FULL, acc.y, lane + 20);
    float az = acc.z + __shfl_sync(FULL, acc.z, lane + 10) + __shfl_sync(FULL, acc.z, lane + 20);
    float aw = acc.w + __shfl_sync(FULL, acc.w, lane + 10) + __shfl_sync(FULL, acc.w, lane + 20);

    const float inv = __fdividef(1.f, den_t);
    const float4 b = ((const float4*)bias2)[sub];
    const float4 r = ((const float4*)(g_res2 + (size_t)d * NCLS))[sub];
    float4 val;
    val.x = ax * inv + b.x + r.x;
    val.y = ay * inv + b.y + r.y;
    val.z = az * inv + b.z + r.z;
    val.w = aw * inv + b.w + r.w;

    float m = (lane < 10) ? fmaxf(fmaxf(val.x, val.y), fmaxf(val.z, val.w)) : -3.4e38f;
#pragma unroll
    for (int o = 16; o; o >>= 1) m = fmaxf(m, __shfl_xor_sync(FULL, m, o));
    float se = (lane < 10)
        ? (__expf(val.x - m) + __expf(val.y - m) + __expf(val.z - m) + __expf(val.w - m))
        : 0.f;
#pragma unroll
    for (int o = 16; o; o >>= 1) se += __shfl_xor_sync(FULL, se, o);
    const float lse = m + logf(se);

    if (lane < 10) {
        float4 o4;
        o4.x = val.x - lse; o4.y = val.y - lse;
        o4.z = val.z - lse; o4.w = val.w - lse;
        ((float4*)(out + (size_t)d * NCLS))[sub] = o4;
    }
}

// ---------------- launch ------------------------------------------------------
extern "C" void kernel_launch(void* const* d_in, const int* in_sizes, int n_in,
                              void* d_out, int out_size)
{
    const float* x   = (const float*)d_in[0];
    const int*   ei  = (const int*)d_in[1];
    const float* W1  = (const float*)d_in[2];
    const float* as1 = (const float*)d_in[3];
    const float* ad1 = (const float*)d_in[4];
    const float* b1  = (const float*)d_in[5];
    const float* W2  = (const float*)d_in[6];
    const float* as2 = (const float*)d_in[7];
    const float* ad2 = (const float*)d_in[8];
    const float* b2  = (const float*)d_in[9];
    const float* r1W = (const float*)d_in[10];
    const float* r1b = (const float*)d_in[11];
    const float* r2W = (const float*)d_in[12];
    const float* r2b = (const float*)d_in[13];

    const int E = in_sizes[1] / 2;

    static cudaStream_t s2 = nullptr;
    static cudaEvent_t ev_fork = nullptr, ev_join = nullptr;
    if (s2 == nullptr) {
        cudaStreamCreate(&s2);
        cudaEventCreateWithFlags(&ev_fork, cudaEventDisableTiming);
        cudaEventCreateWithFlags(&ev_join, cudaEventDisableTiming);
    }

    // main stream: detect (needed by CSR branch), then fork
    k_detect<<<1, 32>>>(ei);
    cudaEventRecord(ev_fork, 0);
    cudaStreamWaitEvent(s2, ev_fork, 0);

    // CSR branch on s2 (independent of gemm1)
    k_zero   <<<(NNODES + 255) / 256, 256, 0, s2>>>();
    k_hist   <<<(E + 255) / 256, 256, 0, s2>>>(ei, E);
    k_scanA  <<<SCAN_BLKS, 1024, 0, s2>>>();
    k_scanB  <<<1, 128, 0, s2>>>();
    k_scanC  <<<SCAN_BLKS, 1024, 0, s2>>>();
    k_scatter<<<(E + 255) / 256, 256, 0, s2>>>(ei, E);
    cudaEventRecord(ev_join, s2);

    // main stream: gemm1 runs concurrently with CSR build
    k_gemm1<<<NNODES / 32, 128>>>(x, W1, r1W, r1b, as1, ad1);
    cudaStreamWaitEvent(0, ev_join, 0);    // fused kernel needs gemm1 + CSR

    k_agg_gemm2<<<(NNODES + 63) / 64, 160>>>(b1, W2, r2W, r2b, as2, ad2);
    k_edge2fin<<<(NNODES + 7) / 8, 256>>>(b2, (float*)d_out);
}

// round 17
// speedup vs baseline: 1.0866x; 1.0866x over previous
#include <cuda_runtime.h>
#include <cstdint>

#define NNODES 100000
#define NFEAT  128
#define HID    128   // 8 heads * 16
#define H1     8
#define NCLS   40
#define NEG    0.2f
#define EMAX   1664000
#define SCAN_BLKS 98   // ceil(100000/1024)

typedef unsigned long long ull;

// ---------------- scratch (device globals; no runtime alloc) ----------------
__device__ __align__(16) float g_h1  [NNODES * HID];
__device__ __align__(16) float g_res1[NNODES * HID];
__device__ __align__(16) float g_as1 [NNODES * H1];
__device__ __align__(16) float g_ad1 [NNODES * H1];
__device__ __align__(16) float g_h   [NNODES * HID];
__device__ __align__(16) float g_h2  [NNODES * NCLS];
__device__ __align__(16) float g_res2[NNODES * NCLS];
__device__ __align__(16) float g_as2 [NNODES];
__device__ __align__(16) float g_ad2 [NNODES];
__device__ int g_deg[NNODES];
__device__ int g_off[NNODES + 1];
__device__ int g_cur[NNODES];
__device__ int g_csr[EMAX];
__device__ int g_bsum[128];
__device__ int g_is64;

// ---------------- f32x2 helpers ----------------------------------------------
__device__ __forceinline__ ull pack2(float v) {
    ull r; asm("mov.b64 %0, {%1,%1};" : "=l"(r) : "f"(v)); return r;
}
__device__ __forceinline__ void unpack2(ull v, float& lo, float& hi) {
    asm("mov.b64 {%0,%1}, %2;" : "=f"(lo), "=f"(hi) : "l"(v));
}
__device__ __forceinline__ void fma2(ull& acc, ull a, ull b) {
    asm("fma.rn.f32x2 %0, %1, %2, %0;" : "+l"(acc) : "l"(a), "l"(b));
}
__device__ __forceinline__ ull mul2(ull a, ull b) {
    ull c; asm("mul.rn.f32x2 %0, %1, %2;" : "=l"(c) : "l"(a), "l"(b)); return c;
}
__device__ __forceinline__ ull add2(ull a, ull b) {
    ull c; asm("add.rn.f32x2 %0, %1, %2;" : "=l"(c) : "l"(a), "l"(b)); return c;
}
__device__ __forceinline__ ull shfl_xor64(ull v, int o) {
    double d = __longlong_as_double((long long)v);
    d = __shfl_xor_sync(0xffffffffu, d, o);
    return (ull)__double_as_longlong(d);
}

// ---------------- edge_index dtype detection (warp-parallel) ------------------
__global__ void k_detect(const int* __restrict__ ei32)
{
    const int lane = threadIdx.x & 31;
    long long s = (long long)ei32[2 * lane + 1] + (long long)ei32[2 * lane + 65];
#pragma unroll
    for (int o = 16; o; o >>= 1)
        s += __shfl_xor_sync(0xffffffffu, s, o);
    if (lane == 0) g_is64 = (s == 0) ? 1 : 0;
}

__device__ __forceinline__ int edge_dst(const int* __restrict__ ei, int E, int e)
{
    return g_is64 ? (int)((const long long*)ei)[E + e] : ei[E + e];
}
__device__ __forceinline__ int edge_src(const int* __restrict__ ei, int E, int e)
{
    return g_is64 ? (int)((const long long*)ei)[e] : ei[e];
}

// ---------------- CSR build ----------------------------------------------------
__global__ void k_zero()
{
    const int i = blockIdx.x * blockDim.x + threadIdx.x;
    if (i < NNODES) { g_deg[i] = 0; g_cur[i] = 0; }
}

__global__ void k_hist(const int* __restrict__ ei, int E)
{
    const int e = blockIdx.x * blockDim.x + threadIdx.x;
    if (e >= E) return;
    atomicAdd(&g_deg[edge_dst(ei, E, e)], 1);
}

__global__ void __launch_bounds__(1024) k_scanA()
{
    __shared__ int wsum[32];
    const int t = threadIdx.x, lane = t & 31, wid = t >> 5;
    const int idx = blockIdx.x * 1024 + t;
    const int v = (idx < NNODES) ? g_deg[idx] : 0;

    int inc = v;
#pragma unroll
    for (int o = 1; o < 32; o <<= 1) {
        int n = __shfl_up_sync(0xffffffffu, inc, o);
        if (lane >= o) inc += n;
    }
    if (lane == 31) wsum[wid] = inc;
    __syncthreads();
    if (wid == 0) {
        int s = wsum[lane];
#pragma unroll
        for (int o = 1; o < 32; o <<= 1) {
            int n = __shfl_up_sync(0xffffffffu, s, o);
            if (lane >= o) s += n;
        }
        wsum[lane] = s;
    }
    __syncthreads();
    const int pre = (wid > 0) ? wsum[wid - 1] : 0;
    if (idx < NNODES) g_off[idx] = pre + inc - v;
    if (t == 1023) g_bsum[blockIdx.x] = pre + inc;
}

__global__ void k_scanB()
{
    __shared__ int sh[128];
    const int t = threadIdx.x;
    const int v = (t < SCAN_BLKS) ? g_bsum[t] : 0;
    sh[t] = v;
    __syncthreads();
#pragma unroll
    for (int o = 1; o < 128; o <<= 1) {
        const int n = (t >= o) ? sh[t - o] : 0;
        __syncthreads();
        sh[t] += n;
        __syncthreads();
    }
    g_bsum[t] = sh[t] - v;
    if (t == 127) g_off[NNODES] = sh[127];
}

__global__ void __launch_bounds__(1024) k_scanC()
{
    const int idx = blockIdx.x * 1024 + threadIdx.x;
    if (idx < NNODES) g_off[idx] += g_bsum[blockIdx.x];
}

__global__ void k_scatter(const int* __restrict__ ei, int E)
{
    const int e = blockIdx.x * blockDim.x + threadIdx.x;
    if (e >= E) return;
    const int d = edge_dst(ei, E, e);
    const int s = edge_src(ei, E, e);
    const int pos = g_off[d] + atomicAdd(&g_cur[d], 1);
    g_csr[pos] = s;
}

// ---------------- Layer 1 node GEMM (f32x2): 32 rows x 256 cols per block ----
__global__ void __launch_bounds__(128) k_gemm1(
        const float* __restrict__ x,
        const float* __restrict__ W1,
        const float* __restrict__ resW,
        const float* __restrict__ res_b,
        const float* __restrict__ att_src,
        const float* __restrict__ att_dst)
{
    __shared__ __align__(16) float xs[128 * 36];  // [k][36]
    const int row0 = blockIdx.x * 32;
    const int t = threadIdx.x;

#pragma unroll 4
    for (int r = 0; r < 32; r++)
        xs[t * 36 + r] = x[(row0 + r) * NFEAT + t];
    __syncthreads();

    ull accA[16], accB[16];
#pragma unroll
    for (int i = 0; i < 16; i++) { accA[i] = 0ull; accB[i] = 0ull; }

    const float* WA = W1 + t;     // stride 128
    const float* WB = resW + t;   // stride 128

#pragma unroll 4
    for (int k = 0; k < 128; k++) {
        const ull wa = pack2(WA[k * 128]);
        const ull wb = pack2(WB[k * 128]);
        const ulonglong2* xp = (const ulonglong2*)(xs + k * 36);
#pragma unroll
        for (int i = 0; i < 8; i++) {
            const ulonglong2 xv = xp[i];
            fma2(accA[2 * i],     xv.x, wa);
            fma2(accA[2 * i + 1], xv.y, wa);
            fma2(accB[2 * i],     xv.x, wb);
            fma2(accB[2 * i + 1], xv.y, wb);
        }
    }

    const ull asp = pack2(att_src[t]);   // (8,16) row-major: head=t>>4
    const ull adp = pack2(att_dst[t]);
    const ull bbp = pack2(res_b[t]);
    const int head = t >> 4;

#pragma unroll
    for (int i = 0; i < 16; i++) {
        const int gr = row0 + 2 * i;
        float lo, hi;
        unpack2(accA[i], lo, hi);
        g_h1[gr * HID + t]       = lo;
        g_h1[(gr + 1) * HID + t] = hi;

        ull vs = mul2(accA[i], asp);
        ull vd = mul2(accA[i], adp);
#pragma unroll
        for (int o = 8; o; o >>= 1) {
            vs = add2(vs, shfl_xor64(vs, o));
            vd = add2(vd, shfl_xor64(vd, o));
        }
        if ((t & 15) == 0) {
            float s0, s1, d0, d1;
            unpack2(vs, s0, s1); unpack2(vd, d0, d1);
            g_as1[gr * H1 + head]       = s0;
            g_as1[(gr + 1) * H1 + head] = s1;
            g_ad1[gr * H1 + head]       = d0;
            g_ad1[(gr + 1) * H1 + head] = d1;
        }

        ull rb = add2(accB[i], bbp);
        unpack2(rb, lo, hi);
        g_res1[gr * HID + t]       = lo;
        g_res1[(gr + 1) * HID + t] = hi;
    }
}

// ---------------- Layer 1 aggregation: warp per dst node, CSR gather ---------
// Lane owns head (lane>>2) -> no shuffles. Streaming hints: g_res1 read-once
// (ldcs), g_h written evict-first (stcs) to keep the g_h1 gather set in L2.
__global__ void k_edge1agg(const float* __restrict__ bias1)
{
    const int d    = (blockIdx.x * blockDim.x + threadIdx.x) >> 5;
    const int lane = threadIdx.x & 31;
    if (d >= NNODES) return;

    const int h = lane >> 2;             // head of this lane's float4
    const float ad = g_ad1[d * H1 + h];

    // self loop
    float l = g_as1[d * H1 + h] + ad;
    l = (l > 0.f) ? l : NEG * l;
    float den = __expf(l);
    float4 v = ((const float4*)(g_h1 + (size_t)d * HID))[lane];
    float4 acc; acc.x = v.x * den; acc.y = v.y * den;
    acc.z = v.z * den; acc.w = v.w * den;

    const int end = g_off[d + 1];
    int e = g_off[d];
    for (; e + 2 <= end; e += 2) {
        const int s0 = g_csr[e];
        const int s1 = g_csr[e + 1];
        float l0 = g_as1[s0 * H1 + h] + ad;
        float l1 = g_as1[s1 * H1 + h] + ad;
        l0 = (l0 > 0.f) ? l0 : NEG * l0;
        l1 = (l1 > 0.f) ? l1 : NEG * l1;
        const float w0 = __expf(l0);
        const float w1 = __expf(l1);
        den += w0 + w1;
        const float4 u0 = ((const float4*)(g_h1 + (size_t)s0 * HID))[lane];
        const float4 u1 = ((const float4*)(g_h1 + (size_t)s1 * HID))[lane];
        acc.x += u0.x * w0; acc.y += u0.y * w0;
        acc.z += u0.z * w0; acc.w += u0.w * w0;
        acc.x += u1.x * w1; acc.y += u1.y * w1;
        acc.z += u1.z * w1; acc.w += u1.w * w1;
    }
    if (e < end) {
        const int s = g_csr[e];
        float ls = g_as1[s * H1 + h] + ad;
        ls = (ls > 0.f) ? ls : NEG * ls;
        const float ew = __expf(ls);
        den += ew;
        const float4 u = ((const float4*)(g_h1 + (size_t)s * HID))[lane];
        acc.x += u.x * ew; acc.y += u.y * ew;
        acc.z += u.z * ew; acc.w += u.w * ew;
    }

    const float inv = __fdividef(1.f, den);
    const float4 b = ((const float4*)bias1)[lane];
    const float4 r = __ldcs(((const float4*)(g_res1 + (size_t)d * HID)) + lane);
    float4 o;
    float t0;
    t0 = acc.x * inv + b.x; o.x = ((t0 > 0.f) ? t0 : (__expf(t0) - 1.f)) + r.x;
    t0 = acc.y * inv + b.y; o.y = ((t0 > 0.f) ? t0 : (__expf(t0) - 1.f)) + r.y;
    t0 = acc.z * inv + b.z; o.z = ((t0 > 0.f) ? t0 : (__expf(t0) - 1.f)) + r.z;
    t0 = acc.w * inv + b.w; o.w = ((t0 > 0.f) ? t0 : (__expf(t0) - 1.f)) + r.w;
    __stcs(((float4*)(g_h + (size_t)d * HID)) + lane, o);
}

// ---------------- Layer 2 node GEMM (f32x2): 64-row tiles, dual-col threads --
__global__ void __launch_bounds__(160) k_gemm2(
        const float* __restrict__ W2,
        const float* __restrict__ res2W,
        const float* __restrict__ res2_b,
        const float* __restrict__ att_src2,
        const float* __restrict__ att_dst2)
{
    __shared__ __align__(16) float xs[128 * 68];   // [c][68]; reused as sred
    const int row0 = blockIdx.x * 64;
    const int t = threadIdx.x;

    for (int idx = t; idx < 64 * 128; idx += 160) {
        const int r = idx >> 7, c = idx & 127;
        const int row = row0 + r;
        xs[c * 68 + r] = (row < NNODES)
            ? __ldcs(g_h + (size_t)row * HID + c) : 0.f;
    }
    __syncthreads();

    const int col = t % 40;
    const int grp = t / 40;

    ull accA[8], accB[8];
#pragma unroll
    for (int i = 0; i < 8; i++) { accA[i] = 0ull; accB[i] = 0ull; }

    const float* WA = W2 + col;
    const float* WB = res2W + col;
#pragma unroll 4
    for (int k = 0; k < 128; k++) {
        const ull wa = pack2(WA[k * NCLS]);
        const ull wb = pack2(WB[k * NCLS]);
        const ulonglong2* xp = (const ulonglong2*)(xs + k * 68 + grp * 16);
#pragma unroll
        for (int i = 0; i < 4; i++) {
            const ulonglong2 xv = xp[i];
            fma2(accA[2 * i],     xv.x, wa);
            fma2(accA[2 * i + 1], xv.y, wa);
            fma2(accB[2 * i],     xv.x, wb);
            fma2(accB[2 * i + 1], xv.y, wb);
        }
    }
    __syncthreads();
    float* sred = xs;

    const float as = att_src2[col];
    const float adw = att_dst2[col];
    const ull bp = pack2(res2_b[col]);
#pragma unroll
    for (int i = 0; i < 8; i++) {
        const int lr = grp * 16 + 2 * i;
        const int gr = row0 + lr;
        float lo, hi;
        unpack2(accA[i], lo, hi);
        sred[lr * NCLS + col]       = lo * as;
        sred[(lr + 1) * NCLS + col] = hi * as;
        sred[64 * NCLS + lr * NCLS + col]       = lo * adw;
        sred[64 * NCLS + (lr + 1) * NCLS + col] = hi * adw;
        float rlo, rhi;
        unpack2(add2(accB[i], bp), rlo, rhi);
        if (gr < NNODES) {
            g_h2  [gr * NCLS + col] = lo;
            g_res2[gr * NCLS + col] = rlo;
        }
        if (gr + 1 < NNODES) {
            g_h2  [(gr + 1) * NCLS + col] = hi;
            g_res2[(gr + 1) * NCLS + col] = rhi;
        }
    }
    __syncthreads();

    if (t < 64 && row0 + t < NNODES) {
        float ss = 0.f, dd = 0.f;
#pragma unroll 8
        for (int c = 0; c < NCLS; c++) {
            ss += sred[t * NCLS + c];
            dd += sred[64 * NCLS + t * NCLS + c];
        }
        g_as2[row0 + t] = ss;
        g_ad2[row0 + t] = dd;
    }
}

// ---------------- Layer 2 aggregation + log_softmax: warp per dst node -------
__global__ void k_edge2fin(const float* __restrict__ bias2,
                           float* __restrict__ out)
{
    const int d    = (blockIdx.x * blockDim.x + threadIdx.x) >> 5;
    const int lane = threadIdx.x & 31;
    if (d >= NNODES) return;

    const int grp = lane / 10;
    const int sub = lane - grp * 10;
    const float ad = g_ad2[d];

    float den = 0.f;
    float4 acc; acc.x = acc.y = acc.z = acc.w = 0.f;

    if (grp == 0) {
        float l = g_as2[d] + ad;
        l = (l > 0.f) ? l : NEG * l;
        const float w = __expf(l);
        den = w;
        const float4 v = ((const float4*)(g_h2 + (size_t)d * NCLS))[sub];
        acc.x = v.x * w; acc.y = v.y * w; acc.z = v.z * w; acc.w = v.w * w;
    }

    if (grp < 3) {
        const int end = g_off[d + 1];
        int e = g_off[d] + grp;
        for (; e + 3 < end; e += 6) {
            const int s0 = g_csr[e];
            const int s1 = g_csr[e + 3];
            float l0 = g_as2[s0] + ad;
            float l1 = g_as2[s1] + ad;
            l0 = (l0 > 0.f) ? l0 : NEG * l0;
            l1 = (l1 > 0.f) ? l1 : NEG * l1;
            const float w0 = __expf(l0);
            const float w1 = __expf(l1);
            den += w0 + w1;
            const float4 v0 = ((const float4*)(g_h2 + (size_t)s0 * NCLS))[sub];
            const float4 v1 = ((const float4*)(g_h2 + (size_t)s1 * NCLS))[sub];
            acc.x += v0.x * w0; acc.y += v0.y * w0;
            acc.z += v0.z * w0; acc.w += v0.w * w0;
            acc.x += v1.x * w1; acc.y += v1.y * w1;
            acc.z += v1.z * w1; acc.w += v1.w * w1;
        }
        if (e < end) {
            const int s = g_csr[e];
            float l = g_as2[s] + ad;
            l = (l > 0.f) ? l : NEG * l;
            const float w = __expf(l);
            den += w;
            const float4 v = ((const float4*)(g_h2 + (size_t)s * NCLS))[sub];
            acc.x += v.x * w; acc.y += v.y * w;
            acc.z += v.z * w; acc.w += v.w * w;
        }
    }

    const unsigned FULL = 0xffffffffu;
    float den_t = den + __shfl_sync(FULL, den, lane + 10)
                      + __shfl_sync(FULL, den, lane + 20);
    float ax = acc.x + __shfl_sync(FULL, acc.x, lane + 10) + __shfl_sync(FULL, acc.x, lane + 20);
    float ay = acc.y + __shfl_sync(FULL, acc.y, lane + 10) + __shfl_sync(FULL, acc.y, lane + 20);
    float az = acc.z + __shfl_sync(FULL, acc.z, lane + 10) + __shfl_sync(FULL, acc.z, lane + 20);
    float aw = acc.w + __shfl_sync(FULL, acc.w, lane + 10) + __shfl_sync(FULL, acc.w, lane + 20);

    const float inv = __fdividef(1.f, den_t);
    const float4 b = ((const float4*)bias2)[sub];
    const float4 r = __ldcs(((const float4*)(g_res2 + (size_t)d * NCLS)) + sub);
    float4 val;
    val.x = ax * inv + b.x + r.x;
    val.y = ay * inv + b.y + r.y;
    val.z = az * inv + b.z + r.z;
    val.w = aw * inv + b.w + r.w;

    float m = (lane < 10) ? fmaxf(fmaxf(val.x, val.y), fmaxf(val.z, val.w)) : -3.4e38f;
#pragma unroll
    for (int o = 16; o; o >>= 1) m = fmaxf(m, __shfl_xor_sync(FULL, m, o));
    float se = (lane < 10)
        ? (__expf(val.x - m) + __expf(val.y - m) + __expf(val.z - m) + __expf(val.w - m))
        : 0.f;
#pragma unroll
    for (int o = 16; o; o >>= 1) se += __shfl_xor_sync(FULL, se, o);
    const float lse = m + logf(se);

    if (lane < 10) {
        float4 o4;
        o4.x = val.x - lse; o4.y = val.y - lse;
        o4.z = val.z - lse; o4.w = val.w - lse;
        ((float4*)(out + (size_t)d * NCLS))[sub] = o4;
    }
}

// ---------------- launch ------------------------------------------------------
extern "C" void kernel_launch(void* const* d_in, const int* in_sizes, int n_in,
                              void* d_out, int out_size)
{
    const float* x   = (const float*)d_in[0];
    const int*   ei  = (const int*)d_in[1];
    const float* W1  = (const float*)d_in[2];
    const float* as1 = (const float*)d_in[3];
    const float* ad1 = (const float*)d_in[4];
    const float* b1  = (const float*)d_in[5];
    const float* W2  = (const float*)d_in[6];
    const float* as2 = (const float*)d_in[7];
    const float* ad2 = (const float*)d_in[8];
    const float* b2  = (const float*)d_in[9];
    const float* r1W = (const float*)d_in[10];
    const float* r1b = (const float*)d_in[11];
    const float* r2W = (const float*)d_in[12];
    const float* r2b = (const float*)d_in[13];

    const int E = in_sizes[1] / 2;

    static cudaStream_t s2 = nullptr;
    static cudaEvent_t ev_fork = nullptr, ev_join = nullptr;
    if (s2 == nullptr) {
        cudaStreamCreate(&s2);
        cudaEventCreateWithFlags(&ev_fork, cudaEventDisableTiming);
        cudaEventCreateWithFlags(&ev_join, cudaEventDisableTiming);
    }

    // fork immediately: the CSR branch (incl. detect) is fully independent
    // of gemm1, which starts at once on the main stream.
    cudaEventRecord(ev_fork, 0);
    cudaStreamWaitEvent(s2, ev_fork, 0);

    k_detect <<<1, 32, 0, s2>>>(ei);
    k_zero   <<<(NNODES + 255) / 256, 256, 0, s2>>>();
    k_hist   <<<(E + 255) / 256, 256, 0, s2>>>(ei, E);
    k_scanA  <<<SCAN_BLKS, 1024, 0, s2>>>();
    k_scanB  <<<1, 128, 0, s2>>>();
    k_scanC  <<<SCAN_BLKS, 1024, 0, s2>>>();
    k_scatter<<<(E + 255) / 256, 256, 0, s2>>>(ei, E);
    cudaEventRecord(ev_join, s2);

    // main stream: gemm1 runs concurrently with the whole CSR branch
    k_gemm1<<<NNODES / 32, 128>>>(x, W1, r1W, r1b, as1, ad1);
    cudaStreamWaitEvent(0, ev_join, 0);    // edge1agg needs gemm1 + CSR

    k_edge1agg<<<(NNODES + 7) / 8, 256>>>(b1);
    k_gemm2  <<<(NNODES + 63) / 64, 160>>>(W2, r2W, r2b, as2, ad2);
    k_edge2fin<<<(NNODES + 7) / 8, 256>>>(b2, (float*)d_out);
}